// round 17
// baseline (speedup 1.0000x reference)
#include <cuda_runtime.h>
#include <cuda_bf16.h>
#include <cstdint>

// GAT layer:  B=8, N=1024, F_IN=25, H=8, D=16
// out = [ relu(h_prime) : 8*1024*128 floats | alpha : 8*8*1024*1024 floats ]
//
//   alpha[b,h,i,j] = adj[i,j]*p[h,j] / S[h,i],  p[j]=exp(ej[j])  (shift-free)
//   h_prime = (A @ Y)/S,  Y[j, h*16+d] = p[h,j]*Wh[h,j,d]
//
// Round 17: occupancy push for the fused kernel — 4 CTAs/SM.
//   smem: GEMM K-tile 64->32, stage 26880B, 2 stages = 53760B (< 228KB/4)
//   regs: __launch_bounds__(256,4) -> <=64; alpha branch restructured
//         (S via FMA first pass; store pass re-loads p via opaque asm load
//          so ptxas can't CSE it into 32 live registers).

#define BQ 8
#define NQ 1024
#define FQ 25
#define HQ 8
#define DQ 16
#define HD 128

__device__ float g_p[BQ * HQ * NQ];      // [b][h][j] fp32
__device__ __align__(16) __nv_bfloat16 g_Yhi[BQ * HD * NQ];  // [b][c][j]
__device__ __align__(16) __nv_bfloat16 g_Ylo[BQ * HD * NQ];  // [b][c][j]
__device__ __align__(16) __nv_bfloat16 g_phi[BQ * HQ * NQ];  // [b][h][j]
__device__ __align__(16) __nv_bfloat16 g_plo[BQ * HQ * NQ];  // [b][h][j]

// ---------------- PTX helpers ----------------
__device__ __forceinline__ uint32_t smem_u32(const void* p) {
    uint32_t a;
    asm("{ .reg .u64 t; cvta.to.shared.u64 t, %1; cvt.u32.u64 %0, t; }"
        : "=r"(a) : "l"(p));
    return a;
}
#define CP_ASYNC16(saddr, gptr)                                                \
    asm volatile("cp.async.cg.shared.global [%0], [%1], 16;"                   \
                 :: "r"(saddr), "l"(gptr) : "memory")
#define CP_COMMIT() asm volatile("cp.async.commit_group;" ::: "memory")
#define CP_WAIT1()  asm volatile("cp.async.wait_group 1;" ::: "memory")
#define LDSM4(r0, r1, r2, r3, addr)                                            \
    asm volatile("ldmatrix.sync.aligned.m8n8.x4.shared.b16 {%0,%1,%2,%3}, [%4];" \
                 : "=r"(r0), "=r"(r1), "=r"(r2), "=r"(r3) : "r"(addr))
#define LDSM2(r0, r1, addr)                                                    \
    asm volatile("ldmatrix.sync.aligned.m8n8.x2.shared.b16 {%0,%1}, [%2];"     \
                 : "=r"(r0), "=r"(r1) : "r"(addr))
#define MMA16816(c, a, b0, b1)                                                 \
    asm volatile("mma.sync.aligned.m16n8k16.row.col.f32.bf16.bf16.f32 "        \
                 "{%0,%1,%2,%3}, {%4,%5,%6,%7}, {%8,%9}, {%0,%1,%2,%3};"       \
                 : "+f"((c)[0]), "+f"((c)[1]), "+f"((c)[2]), "+f"((c)[3])      \
                 : "r"((a)[0]), "r"((a)[1]), "r"((a)[2]), "r"((a)[3]),         \
                   "r"(b0), "r"(b1))
// opaque global load (not CSE'd against regular loads)
__device__ __forceinline__ float4 ldg_nc_v4(const float* p) {
    float4 v;
    asm volatile("ld.global.nc.v4.f32 {%0,%1,%2,%3}, [%4];"
                 : "=f"(v.x), "=f"(v.y), "=f"(v.z), "=f"(v.w) : "l"(p));
    return v;
}

// ---------------- K1: prep, no reductions ----------------
__global__ __launch_bounds__(256) void k1(const float* __restrict__ x,
                                          const float* __restrict__ W,
                                          const float* __restrict__ a) {
    int bh = blockIdx.x >> 2, chunk = blockIdx.x & 3;
    int b = bh >> 3, h = bh & 7;
    int tid = threadIdx.x;
    __shared__ float Ws[FQ * DQ];
    __shared__ float as[DQ];

    for (int i = tid; i < FQ * DQ; i += 256) Ws[i] = W[h * FQ * DQ + i];
    if (tid < DQ) as[tid] = a[h * 2 * DQ + DQ + tid];
    __syncthreads();

    int j = chunk * 256 + tid;
    const float* xr = x + ((size_t)(b * NQ + j)) * FQ;
    float xf[FQ];
#pragma unroll
    for (int f = 0; f < FQ; f++) xf[f] = xr[f];

    float wh[DQ];
#pragma unroll
    for (int d = 0; d < DQ; d++) {
        float s = 0.f;
#pragma unroll
        for (int f = 0; f < FQ; f++) s += xf[f] * Ws[f * DQ + d];
        wh[d] = s;
    }
    float e = 0.f;
#pragma unroll
    for (int d = 0; d < DQ; d++) e += wh[d] * as[d];

    float p = expf(e);  // shift-free softmax (exactly invariant; no overflow)
    g_p[bh * NQ + j] = p;
    __nv_bfloat16 phi = __float2bfloat16(p);
    g_phi[bh * NQ + j] = phi;
    g_plo[bh * NQ + j] = __float2bfloat16(p - __bfloat162float(phi));
#pragma unroll
    for (int d = 0; d < DQ; d++) {
        float yv = wh[d] * p;
        __nv_bfloat16 hi = __float2bfloat16(yv);
        __nv_bfloat16 lo = __float2bfloat16(yv - __bfloat162float(hi));
        size_t o = ((size_t)(b * HD + h * DQ + d)) * NQ + j;
        g_Yhi[o] = hi;
        g_Ylo[o] = lo;
    }
}

// ---------------- K23: fused GEMM + alpha ------------------------------
// GEMM blocks (128): CTA tile C[64,128], 8 warps (2m x 4n), K-loop 32 x 32.
// stage (row stride 80B): A 64x80=5120, Bh/Bl 128x80=10240 ea,
//                         Ph/Pl 8x80=640 ea  -> 26880 B; 2 stages = 53760 B.
#define K2_STAGE 26880
#define K2_SMEM  (2 * K2_STAGE)
#define OFF_BH 5120
#define OFF_BL 15360
#define OFF_PH 25600
#define OFF_PL 26240
#define LDB 80
#define NGEMM 128

__device__ __forceinline__ void k2_fill_y(uint32_t sbase, int b, int j0,
                                          int tid) {
#pragma unroll
    for (int t = 0; t < 2; t++) {  // Bh/Bl: 512 16B chunks each
        int idx = tid + t * 256;
        int row = idx >> 2, ch = idx & 3;
        size_t go = ((size_t)(b * HD + row)) * NQ + j0 + ch * 8;
        CP_ASYNC16(sbase + OFF_BH + row * LDB + ch * 16, (const void*)(g_Yhi + go));
        CP_ASYNC16(sbase + OFF_BL + row * LDB + ch * 16, (const void*)(g_Ylo + go));
    }
    if (tid < 64) {  // Ph/Pl: 32 chunks each (8 rows x 64B)
        int row = (tid & 31) >> 2, ch = tid & 3;
        size_t go = ((size_t)(b * HQ + row)) * NQ + j0 + ch * 8;
        if (tid < 32)
            CP_ASYNC16(sbase + OFF_PH + row * LDB + ch * 16, (const void*)(g_phi + go));
        else
            CP_ASYNC16(sbase + OFF_PL + row * LDB + ch * 16, (const void*)(g_plo + go));
    }
}

__device__ __forceinline__ void k2_ldg_a(int4* av, const int* adj, int b,
                                         int i0, int j0, int tid) {
#pragma unroll
    for (int t = 0; t < 2; t++) {  // 64 rows x 8 int4 chunks
        int idx = tid + t * 256;
        int row = idx >> 3, ch = idx & 7;
        av[t] = *(const int4*)(adj + ((size_t)(b * NQ + i0 + row)) * NQ + j0 + ch * 4);
    }
}

__device__ __forceinline__ void k2_sts_a(const int4* av, uint32_t As, int tid) {
#pragma unroll
    for (int t = 0; t < 2; t++) {
        int idx = tid + t * 256;
        int row = idx >> 3, ch = idx & 7;
        uint32_t w0 = (av[t].x ? 0x3F80u : 0u) | ((av[t].y ? 0x3F80u : 0u) << 16);
        uint32_t w1 = (av[t].z ? 0x3F80u : 0u) | ((av[t].w ? 0x3F80u : 0u) << 16);
        asm volatile("st.shared.v2.b32 [%0], {%1, %2};"
                     :: "r"(As + row * LDB + ch * 8), "r"(w0), "r"(w1) : "memory");
    }
}

__global__ __launch_bounds__(256, 4) void k23(const int* __restrict__ adj,
                                              float* __restrict__ out1,
                                              float* __restrict__ alpha) {
    extern __shared__ char smem_raw[];
    int tid = threadIdx.x;

    if (blockIdx.x >= NGEMM) {
        // ---------- alpha: warp-per-row, sync-free, two-pass low-reg ----------
        int wid = tid >> 5, lid = tid & 31;
        int r = (blockIdx.x - NGEMM) * 8 + wid;  // global row 0..8191
        int b = r >> 10;
        int i = r & 1023;

        float4 af[8];
        const int* arow = adj + ((size_t)(b * NQ + i)) * NQ;
#pragma unroll
        for (int c = 0; c < 8; c++) {
            int4 a4 = *(const int4*)(arow + c * 128 + lid * 4);
            af[c] = make_float4((float)a4.x, (float)a4.y, (float)a4.z, (float)a4.w);
        }

#pragma unroll
        for (int h = 0; h < HQ; h++) {
            const float* prow = g_p + (b * HQ + h) * NQ;
            // pass 1: S only (no v[] kept — register budget)
            float s0 = 0.f, s1 = 0.f, s2 = 0.f, s3 = 0.f;
#pragma unroll
            for (int c = 0; c < 8; c++) {
                float4 pv = *(const float4*)(prow + c * 128 + lid * 4);
                s0 = fmaf(af[c].x, pv.x, s0);
                s1 = fmaf(af[c].y, pv.y, s1);
                s2 = fmaf(af[c].z, pv.z, s2);
                s3 = fmaf(af[c].w, pv.w, s3);
            }
            float s = (s0 + s1) + (s2 + s3);
#pragma unroll
            for (int o = 16; o; o >>= 1)
                s += __shfl_xor_sync(0xffffffffu, s, o);
            float inv = 1.0f / s;

            // pass 2: re-load p (opaque, L1-resident) and store masked*inv
            float* orow = alpha + (((size_t)(b * HQ + h) * NQ + i)) * NQ;
#pragma unroll
            for (int c = 0; c < 8; c++) {
                float4 pv = ldg_nc_v4(prow + c * 128 + lid * 4);
                float4 o;
                o.x = af[c].x * pv.x * inv;
                o.y = af[c].y * pv.y * inv;
                o.z = af[c].z * pv.z * inv;
                o.w = af[c].w * pv.w * inv;
                __stcs((float4*)(orow + c * 128 + lid * 4), o);
            }
        }
        return;
    }

    // ---------------- GEMM part ----------------
    uint32_t sb = smem_u32(smem_raw);
    float* Ssm = (float*)smem_raw;  // reused over stage-0 A after the loop

    int wid = tid >> 5, lid = tid & 31;
    int b = blockIdx.x >> 4;
    int i0 = (blockIdx.x & 15) * 64;
    int wm = wid & 1, wn = wid >> 1;  // warp tile: M32 x N32

    float acc[2][4][4];
    float accS[2][4];
#pragma unroll
    for (int f = 0; f < 2; f++) {
#pragma unroll
        for (int j = 0; j < 4; j++)
#pragma unroll
            for (int q = 0; q < 4; q++) acc[f][j][q] = 0.f;
#pragma unroll
        for (int q = 0; q < 4; q++) accS[f][q] = 0.f;
    }

    int la  = (lid & 7) + ((lid >> 3) & 1) * 8;
    int lk  = (lid >> 4) * 8;
    int lnr = (lid & 7) + (lid >> 4) * 8;
    int lbk = ((lid >> 3) & 1) * 8;
    int pr  = lid & 7;

    int4 av[2];
    k2_ldg_a(av, adj, b, i0, 0, tid);
    k2_fill_y(sb, b, 0, tid);
    CP_COMMIT();
    k2_fill_y(sb + K2_STAGE, b, 32, tid);
    CP_COMMIT();

    for (int kt = 0; kt < 32; kt++) {
        uint32_t As = sb + (kt & 1) * K2_STAGE;
        uint32_t Bhs = As + OFF_BH, Bls = As + OFF_BL;
        uint32_t Phs = As + OFF_PH, Pls = As + OFF_PL;

        k2_sts_a(av, As, tid);                       // adj -> bf16 in smem
        if (kt + 1 < 32) k2_ldg_a(av, adj, b, i0, (kt + 1) * 32, tid);

        CP_WAIT1();
        __syncthreads();

#pragma unroll
        for (int kk = 0; kk < 2; kk++) {
            uint32_t a[2][4], bh[2][4], bl[2][4];
#pragma unroll
            for (int f = 0; f < 2; f++)
                LDSM4(a[f][0], a[f][1], a[f][2], a[f][3],
                      As + (uint32_t)((wm * 32 + f * 16 + la) * LDB +
                                      (kk * 16 + lk) * 2));
#pragma unroll
            for (int g = 0; g < 2; g++) {
                uint32_t ro = (uint32_t)((wn * 32 + g * 16 + lnr) * LDB +
                                         (kk * 16 + lbk) * 2);
                LDSM4(bh[g][0], bh[g][1], bh[g][2], bh[g][3], Bhs + ro);
                LDSM4(bl[g][0], bl[g][1], bl[g][2], bl[g][3], Bls + ro);
            }
#pragma unroll
            for (int f = 0; f < 2; f++)
#pragma unroll
                for (int j = 0; j < 4; j++) {
                    int g = j >> 1, jj = j & 1;
                    MMA16816(acc[f][j], a[f], bh[g][jj * 2], bh[g][jj * 2 + 1]);
                    MMA16816(acc[f][j], a[f], bl[g][jj * 2], bl[g][jj * 2 + 1]);
                }
            if (wn == 0) {  // S via P tiles (n=8 heads), reuse A fragments
                uint32_t pro = (uint32_t)(pr * LDB + (kk * 16 + lbk) * 2);
                uint32_t ph0, ph1, pl0, pl1;
                LDSM2(ph0, ph1, Phs + pro);
                LDSM2(pl0, pl1, Pls + pro);
#pragma unroll
                for (int f = 0; f < 2; f++) {
                    MMA16816(accS[f], a[f], ph0, ph1);
                    MMA16816(accS[f], a[f], pl0, pl1);
                }
            }
        }
        __syncthreads();
        if (kt + 2 < 32) k2_fill_y(sb + (kt & 1) * K2_STAGE, b, (kt + 2) * 32, tid);
        CP_COMMIT();  // uniform group counting
    }

    // publish S (warps wn==0 cover rows 0-63), then normalized epilogue
    if (wn == 0) {
#pragma unroll
        for (int f = 0; f < 2; f++) {
            int r = wm * 32 + f * 16 + (lid >> 2);
            int c = (lid & 3) * 2;
            Ssm[r * 8 + c]           = accS[f][0];
            Ssm[r * 8 + c + 1]       = accS[f][1];
            Ssm[(r + 8) * 8 + c]     = accS[f][2];
            Ssm[(r + 8) * 8 + c + 1] = accS[f][3];
        }
    }
    __syncthreads();

#pragma unroll
    for (int f = 0; f < 2; f++) {
        int rl = wm * 32 + f * 16 + (lid >> 2);
        int rh = rl + 8;
#pragma unroll
        for (int j = 0; j < 4; j++) {
            int cbase = wn * 32 + j * 8;
            int c0 = cbase + (lid & 3) * 2;
            int h = cbase >> 4;
            float invLo = 1.0f / Ssm[rl * 8 + h];
            float invHi = 1.0f / Ssm[rh * 8 + h];
            float2 vlo, vhi;
            vlo.x = fmaxf(acc[f][j][0] * invLo, 0.f);
            vlo.y = fmaxf(acc[f][j][1] * invLo, 0.f);
            vhi.x = fmaxf(acc[f][j][2] * invHi, 0.f);
            vhi.y = fmaxf(acc[f][j][3] * invHi, 0.f);
            *(float2*)(out1 + ((size_t)(b * NQ + i0 + rl)) * HD + c0) = vlo;
            *(float2*)(out1 + ((size_t)(b * NQ + i0 + rh)) * HD + c0) = vhi;
        }
    }
}

// ---------------- launch ----------------
extern "C" void kernel_launch(void* const* d_in, const int* in_sizes, int n_in,
                              void* d_out, int out_size) {
    const float* x   = (const float*)d_in[0];  // node_feats (8,1024,25)
    const int*   adj = (const int*)d_in[1];    // adj (8,1024,1024)
    const float* W   = (const float*)d_in[2];  // W (8,25,16)
    const float* a   = (const float*)d_in[3];  // a (8,32,1)

    float* out1  = (float*)d_out;                        // relu(h_prime)
    float* alpha = (float*)d_out + (size_t)BQ * NQ * HD; // alpha

    static int smem_set = 0;
    if (!smem_set) {
        cudaFuncSetAttribute(k23, cudaFuncAttributeMaxDynamicSharedMemorySize,
                             K2_SMEM);
        smem_set = 1;
    }

    k1<<<256, 256>>>(x, W, a);
    k23<<<NGEMM + BQ * NQ / 8, 256, K2_SMEM>>>(adj, out1, alpha);
}